// round 6
// baseline (speedup 1.0000x reference)
#include <cuda_runtime.h>

// ---------------------------------------------------------------------------
// Problem dims
// ---------------------------------------------------------------------------
#define TSTEPS 512
#define NB     64
#define HID    256
#define MROWS  (TSTEPS * NB)      // 32768
#define NCOLS  1024               // 4*HID
#define KDIM   256
#define NCLASS 5

#define GRID_REC 128
#define NJ   8                     // j per CTA
#define NBL  32                    // batches per CTA
#define FULLMASK 0xffffffffu

// ---------------------------------------------------------------------------
// Scratch (static __device__ arrays: allocation-free, allowed)
// ---------------------------------------------------------------------------
__device__ __align__(128) float g_Z [2u * MROWS * NCOLS];   // gate preactivations
__device__ __align__(128) float g_H1[2u * MROWS * HID];     // layer-1 hidden outputs
__device__ __align__(128) float g_H2[2u * MROWS * HID];     // layer-2 hidden outputs
__device__ __align__(128) float g_hT[2][2 * 16384];         // dbl-buffered h, [j][b], per dir
__device__ __align__(128) unsigned g_flags[2][4][32];       // [layer][group][producer jb]
__device__ int g_tok32 = 1;                                 // token dtype flag

// ---------------------------------------------------------------------------
// Acquire/release primitives (single-hop message passing, no fences/atomics)
// ---------------------------------------------------------------------------
__device__ __forceinline__ unsigned ld_acquire(const unsigned* p) {
    unsigned v;
    asm volatile("ld.acquire.gpu.global.u32 %0, [%1];" : "=r"(v) : "l"(p) : "memory");
    return v;
}
__device__ __forceinline__ void st_release(unsigned* p, unsigned v) {
    asm volatile("st.release.gpu.global.u32 [%0], %1;" :: "l"(p), "r"(v) : "memory");
}

// ---------------------------------------------------------------------------
// Math helpers
// ---------------------------------------------------------------------------
__device__ __forceinline__ float fsig(float x) {
    x = fminf(fmaxf(x, -30.f), 30.f);
    return __fdividef(1.f, 1.f + __expf(-x));
}
__device__ __forceinline__ float ftanh_(float x) {
    x = fminf(fmaxf(x, -15.f), 15.f);
    float e = __expf(-2.f * x);
    return __fdividef(1.f - e, 1.f + e);
}
__device__ __forceinline__ int load_token(const void* tokens, int is32, int idx) {
    if (is32) return ((const int*)tokens)[idx];
    return (int)((const long long*)tokens)[idx];
}

// ---------------------------------------------------------------------------
// Prep: zero the flag sets (needed every replay) + token dtype probe.
// ---------------------------------------------------------------------------
__global__ void prep_kernel(const void* __restrict__ tokens) {
    __shared__ int flag;
    const int tid = threadIdx.x;
    if (tid < 256) ((unsigned*)g_flags)[tid] = 0u;
    if (tid == 0) flag = 0;
    __syncthreads();
    const int* p = (const int*)tokens;
    int local = 0;
    for (int i = 1 + 2 * tid; i < MROWS; i += 2 * 256) local |= p[i];
    if (local) atomicOr(&flag, 1);
    __syncthreads();
    if (tid == 0) g_tok32 = (flag != 0) ? 1 : 0;
}

// ---------------------------------------------------------------------------
// SGEMM: C[dir] = A @ W[dir] + bias[dir]   (unchanged)
// ---------------------------------------------------------------------------
__global__ void __launch_bounds__(256) gemm_kernel(
    const float* __restrict__ embed,
    const void*  __restrict__ tokens,
    const float* __restrict__ W_fw,
    const float* __restrict__ W_bw,
    const float* __restrict__ b_fw,
    const float* __restrict__ b_bw,
    int mode)
{
    __shared__ __align__(16) float As[16][132];
    __shared__ __align__(16) float Bs[16][128];
    __shared__ int sTok[128];

    const int tid = threadIdx.x;
    const int dir = blockIdx.z;
    const int m0  = blockIdx.y * 128;
    const int n0  = blockIdx.x * 128;

    const float* Wm   = dir ? W_bw : W_fw;
    const float* bias = dir ? b_bw : b_fw;

    if (mode == 0 && tid < 128) {
        int r = m0 + tid;
        int s = r >> 6, b = r & 63;
        int tt = (dir == 0) ? s : (TSTEPS - 1 - s);
        sTok[tid] = load_token(tokens, g_tok32, b * TSTEPS + tt);
    }
    __syncthreads();

    const int ty = tid >> 4;
    const int tx = tid & 15;

    float acc[8][8];
#pragma unroll
    for (int i = 0; i < 8; i++)
#pragma unroll
        for (int j = 0; j < 8; j++) acc[i][j] = 0.f;

    for (int kt = 0; kt < KDIM; kt += 16) {
#pragma unroll
        for (int i = 0; i < 2; i++) {
            int idx = tid + i * 256;
            int m   = idx >> 2;
            int kq  = idx & 3;
            const float* arow;
            if (mode == 0) arow = embed + (size_t)sTok[m] * KDIM;
            else           arow = g_H1 + (size_t)dir * MROWS * HID + (size_t)(m0 + m) * HID;
            float4 v = *(const float4*)(arow + kt + kq * 4);
            As[kq * 4 + 0][m] = v.x;
            As[kq * 4 + 1][m] = v.y;
            As[kq * 4 + 2][m] = v.z;
            As[kq * 4 + 3][m] = v.w;
        }
#pragma unroll
        for (int i = 0; i < 2; i++) {
            int idx = tid + i * 256;
            int k   = idx >> 5;
            int nq  = idx & 31;
            *(float4*)&Bs[k][nq * 4] =
                *(const float4*)(Wm + (size_t)(kt + k) * NCOLS + n0 + nq * 4);
        }
        __syncthreads();

#pragma unroll
        for (int kk = 0; kk < 16; kk++) {
            float a[8], bb[8];
            *(float4*)&a[0]  = *(const float4*)&As[kk][ty * 8];
            *(float4*)&a[4]  = *(const float4*)&As[kk][ty * 8 + 4];
            *(float4*)&bb[0] = *(const float4*)&Bs[kk][tx * 8];
            *(float4*)&bb[4] = *(const float4*)&Bs[kk][tx * 8 + 4];
#pragma unroll
            for (int i = 0; i < 8; i++)
#pragma unroll
                for (int j = 0; j < 8; j++)
                    acc[i][j] = fmaf(a[i], bb[j], acc[i][j]);
        }
        __syncthreads();
    }

    float bv[8];
#pragma unroll
    for (int j = 0; j < 8; j++) bv[j] = bias[n0 + tx * 8 + j];

    float* Cd = g_Z + (size_t)dir * MROWS * NCOLS;
#pragma unroll
    for (int i = 0; i < 8; i++) {
        size_t r = (size_t)(m0 + ty * 8 + i);
        float* cp = Cd + r * NCOLS + n0 + tx * 8;
        float4 o0, o1;
        o0.x = acc[i][0] + bv[0]; o0.y = acc[i][1] + bv[1];
        o0.z = acc[i][2] + bv[2]; o0.w = acc[i][3] + bv[3];
        o1.x = acc[i][4] + bv[4]; o1.y = acc[i][5] + bv[5];
        o1.z = acc[i][6] + bv[6]; o1.w = acc[i][7] + bv[7];
        *(float4*)cp       = o0;
        *((float4*)cp + 1) = o1;
    }
}

// ---------------------------------------------------------------------------
// Recurrent phase. 128 CTAs x 256 thr. CTA = (dir, jb in 0..31, bb in 0..1).
// Thread = (bl, jl), tid = bl*8 + jl. Warp = 4 b x 8 jl.
//
// Sync: flag[jb] = s+1 published with one st.release.gpu after __syncthreads
// (HB-transitive). Consumers: each warp polls all 32 flags (lane p reads
// flag[p] with ld.acquire.gpu) + ballot; then proceeds independently.
// h consumed straight from L2 via per-warp LDG + shfl (no smem staging,
// no in-loop extra barriers). Depth-2 LDG pipeline across the 32 chunks.
// ---------------------------------------------------------------------------
__global__ void __launch_bounds__(256, 1) rec_kernel(
    const float* __restrict__ U_fw,
    const float* __restrict__ U_bw,
    int layer)
{
    __shared__ __align__(16) float sU[NJ * 4 * KDIM];   // 32 KB

    const int cid = blockIdx.x;
    const int dir = cid >> 6;
    const int rem = cid & 63;
    const int jb  = rem >> 1;               // 0..31 (also: this CTA's flag index)
    const int bb  = rem & 1;                // 0..1
    const int j0  = jb * NJ;
    const int b0  = bb * NBL;
    const int tid = threadIdx.x;
    const int w    = tid >> 5;              // warp 0..7
    const int lane = tid & 31;
    const int bl  = tid >> 3;               // 0..31
    const int jl  = tid & 7;                // 0..7
    const int blw = lane >> 3;              // b within warp, 0..3
    const int b   = b0 + bl;
    const int j   = j0 + jl;

    const int grp = dir * 2 + bb;
    unsigned* flags = g_flags[layer][grp];

    const float* U = dir ? U_bw : U_fw;

    // Cache U columns: sU[(k*NJ + jj)*4 + g] = U[k][g*HID + j0+jj]
    for (int idx = tid; idx < NJ * 4 * KDIM; idx += 256) {
        int g  = idx & 3;
        int jj = (idx >> 2) & (NJ - 1);
        int k  = idx >> 5;
        sU[idx] = U[(size_t)k * NCOLS + g * HID + j0 + jj];
    }
    __syncthreads();

    const float4* U4 = (const float4*)sU;
    const float* Zd  = g_Z + (size_t)dir * MROWS * NCOLS;
    float* Hd        = (layer ? g_H2 : g_H1) + (size_t)dir * MROWS * HID;
    float* hTdir0    = g_hT[0] + dir * 16384;
    float* hTdir1    = g_hT[1] + dir * 16384;

    // chunk-load lane mapping: lane -> (kl, blx)
    const int kl   = lane >> 2;             // 0..7
    const int blx  = lane & 3;              // 0..3
    const int boff = b0 + 4 * w + blx;      // global b this lane loads

    // first-step Z
    size_t zrow0 = ((size_t)b) * NCOLS;
    float4 z;
    z.x = Zd[zrow0 + 0 * HID + j];
    z.y = Zd[zrow0 + 1 * HID + j];
    z.z = Zd[zrow0 + 2 * HID + j];
    z.w = Zd[zrow0 + 3 * HID + j];

    float c = 0.f;

    for (int s = 0; s < TSTEPS; s++) {
        float4 acc = z;

        if (s > 0) {
            // ---- wait: all 32 producers have published h[s-1] ----
            const unsigned tgt = (unsigned)s;
            while (__ballot_sync(FULLMASK, ld_acquire(&flags[lane]) < tgt)) { }

            // ---- consume: 32 chunks of 8 k-rows via LDG + shfl ----
            const float* src = ((s - 1) & 1) ? hTdir1 : hTdir0;
            float v0 = __ldcg(&src[(0 * 8 + kl) * 64 + boff]);
            float v1 = __ldcg(&src[(1 * 8 + kl) * 64 + boff]);
#pragma unroll 4
            for (int p = 0; p < 32; p++) {
                float v = v0;
                v0 = v1;
                if (p < 30) v1 = __ldcg(&src[((p + 2) * 8 + kl) * 64 + boff]);
#pragma unroll
                for (int q = 0; q < 8; q++) {
                    float  hv = __shfl_sync(FULLMASK, v, q * 4 + blw);
                    float4 u  = U4[(p * 8 + q) * NJ + jl];
                    acc.x = fmaf(u.x, hv, acc.x);
                    acc.y = fmaf(u.y, hv, acc.y);
                    acc.z = fmaf(u.z, hv, acc.z);
                    acc.w = fmaf(u.w, hv, acc.w);
                }
            }
        }

        // ---- activations ----
        float ig = fsig(acc.x);
        float fg = fsig(acc.y);
        float gg = ftanh_(acc.z);
        float og = fsig(acc.w);
        c = fg * c + ig * gg;
        float h = og * ftanh_(c);

        // publish h for next step (dbl-buffered, [j][b])
        float* hTbuf = (s & 1) ? hTdir1 : hTdir0;
        hTbuf[j * 64 + b] = h;

        // prefetch Z[s+1] (independent of peers)
        if (s < TSTEPS - 1) {
            size_t zrow = ((size_t)(s + 1) * NB + b) * NCOLS;
            z.x = Zd[zrow + 0 * HID + j];
            z.y = Zd[zrow + 1 * HID + j];
            z.z = Zd[zrow + 2 * HID + j];
            z.w = Zd[zrow + 3 * HID + j];
        }

        __syncthreads();                      // all warps' h stores done (HB)
        if (tid == 0 && s < TSTEPS - 1)
            st_release(&flags[jb], (unsigned)(s + 1));   // single-hop publish

        // sequence output (off critical path)
        Hd[((size_t)s * NB + b) * HID + j] = h;
    }
}

// ---------------------------------------------------------------------------
// Output head: concat(fw, bw) @ dense_W + b, softmax over 5 classes.
// ---------------------------------------------------------------------------
__global__ void __launch_bounds__(256) dense_kernel(
    const float* __restrict__ Wd,
    const float* __restrict__ bd,
    float* __restrict__ out)
{
    __shared__ float sW[2 * HID * NCLASS];
    __shared__ float sb[NCLASS];
    const int tid = threadIdx.x;
    for (int i = tid; i < 2 * HID * NCLASS; i += 256) sW[i] = Wd[i];
    if (tid < NCLASS) sb[tid] = bd[tid];
    __syncthreads();

    int gid = blockIdx.x * 256 + tid;      // b*512 + t
    int b = gid >> 9, t = gid & 511;

    const float* hf = g_H2 + ((size_t)t * NB + b) * HID;
    const float* hb = g_H2 + (size_t)MROWS * HID + ((size_t)(TSTEPS - 1 - t) * NB + b) * HID;

    float acc[NCLASS];
#pragma unroll
    for (int cc = 0; cc < NCLASS; cc++) acc[cc] = sb[cc];

    for (int jj = 0; jj < HID; jj++) {
        float v = hf[jj];
#pragma unroll
        for (int cc = 0; cc < NCLASS; cc++)
            acc[cc] = fmaf(v, sW[jj * NCLASS + cc], acc[cc]);
    }
    for (int jj = 0; jj < HID; jj++) {
        float v = hb[jj];
#pragma unroll
        for (int cc = 0; cc < NCLASS; cc++)
            acc[cc] = fmaf(v, sW[(HID + jj) * NCLASS + cc], acc[cc]);
    }

    float m = acc[0];
#pragma unroll
    for (int cc = 1; cc < NCLASS; cc++) m = fmaxf(m, acc[cc]);
    float e[NCLASS], sum = 0.f;
#pragma unroll
    for (int cc = 0; cc < NCLASS; cc++) { e[cc] = __expf(acc[cc] - m); sum += e[cc]; }
    float inv = __fdividef(1.f, sum);
#pragma unroll
    for (int cc = 0; cc < NCLASS; cc++) out[(size_t)gid * NCLASS + cc] = e[cc] * inv;
}

// ---------------------------------------------------------------------------
// Launcher (graph-capturable: kernel launches only, default stream)
// ---------------------------------------------------------------------------
extern "C" void kernel_launch(void* const* d_in, const int* in_sizes, int n_in,
                              void* d_out, int out_size)
{
    const void*  tokens  = d_in[0];
    const float* embed   = (const float*)d_in[1];
    const float* fw_W1   = (const float*)d_in[2];
    const float* fw_U1   = (const float*)d_in[3];
    const float* fw_b1   = (const float*)d_in[4];
    const float* fw_W2   = (const float*)d_in[5];
    const float* fw_U2   = (const float*)d_in[6];
    const float* fw_b2   = (const float*)d_in[7];
    const float* bw_W1   = (const float*)d_in[8];
    const float* bw_U1   = (const float*)d_in[9];
    const float* bw_b1   = (const float*)d_in[10];
    const float* bw_W2   = (const float*)d_in[11];
    const float* bw_U2   = (const float*)d_in[12];
    const float* bw_b2   = (const float*)d_in[13];
    const float* dense_W = (const float*)d_in[14];
    const float* dense_b = (const float*)d_in[15];
    float* out = (float*)d_out;

    prep_kernel<<<1, 256>>>(tokens);

    gemm_kernel<<<dim3(8, 256, 2), 256>>>(embed, tokens, fw_W1, bw_W1, fw_b1, bw_b1, 0);
    rec_kernel<<<GRID_REC, 256>>>(fw_U1, bw_U1, 0);
    gemm_kernel<<<dim3(8, 256, 2), 256>>>(embed, tokens, fw_W2, bw_W2, fw_b2, bw_b2, 1);
    rec_kernel<<<GRID_REC, 256>>>(fw_U2, bw_U2, 1);
    dense_kernel<<<MROWS / 256, 256>>>(dense_W, dense_b, out);
}

// round 7
// speedup vs baseline: 2.1011x; 2.1011x over previous
#include <cuda_runtime.h>

// ---------------------------------------------------------------------------
// Problem dims
// ---------------------------------------------------------------------------
#define TSTEPS 512
#define NB     64
#define HID    256
#define MROWS  (TSTEPS * NB)      // 32768
#define NCOLS  1024               // 4*HID
#define KDIM   256
#define NCLASS 5

#define GRID_REC 128
#define NJ   8                     // j per CTA
#define NBL  32                    // batches per CTA
#define FULLMASK 0xffffffffu
#define REC_SMEM ((NJ * 4 * KDIM + KDIM * NBL) * 4)   // 32KB U + 32KB h

// ---------------------------------------------------------------------------
// Scratch (static __device__ arrays: allocation-free, allowed)
// ---------------------------------------------------------------------------
__device__ __align__(128) float g_Z [2u * MROWS * NCOLS];   // gate preactivations
__device__ __align__(128) float g_H1[2u * MROWS * HID];     // layer-1 hidden outputs
__device__ __align__(128) float g_H2[2u * MROWS * HID];     // layer-2 hidden outputs
__device__ __align__(128) float g_hT[2][2 * 16384];         // dbl-buffered h, [j][b], per dir
__device__ __align__(128) unsigned g_flags[2][4][32];       // [layer][group][producer jb]
__device__ int g_tok32 = 1;                                 // token dtype flag

// ---------------------------------------------------------------------------
// Single-hop message passing primitives
// ---------------------------------------------------------------------------
__device__ __forceinline__ unsigned ld_acquire(const unsigned* p) {
    unsigned v;
    asm volatile("ld.acquire.gpu.global.u32 %0, [%1];" : "=r"(v) : "l"(p) : "memory");
    return v;
}
__device__ __forceinline__ void st_release(unsigned* p, unsigned v) {
    asm volatile("st.release.gpu.global.u32 [%0], %1;" :: "l"(p), "r"(v) : "memory");
}

// ---------------------------------------------------------------------------
// Math helpers
// ---------------------------------------------------------------------------
__device__ __forceinline__ float fsig(float x) {
    x = fminf(fmaxf(x, -30.f), 30.f);
    return __fdividef(1.f, 1.f + __expf(-x));
}
__device__ __forceinline__ float ftanh_(float x) {
    x = fminf(fmaxf(x, -15.f), 15.f);
    float e = __expf(-2.f * x);
    return __fdividef(1.f - e, 1.f + e);
}
__device__ __forceinline__ int load_token(const void* tokens, int is32, int idx) {
    if (is32) return ((const int*)tokens)[idx];
    return (int)((const long long*)tokens)[idx];
}

// ---------------------------------------------------------------------------
// Prep: zero flags (graph replays reuse state) + token dtype probe.
// ---------------------------------------------------------------------------
__global__ void prep_kernel(const void* __restrict__ tokens) {
    __shared__ int flag;
    const int tid = threadIdx.x;
    if (tid < 256) ((unsigned*)g_flags)[tid] = 0u;
    if (tid == 0) flag = 0;
    __syncthreads();
    const int* p = (const int*)tokens;
    int local = 0;
    for (int i = 1 + 2 * tid; i < MROWS; i += 2 * 256) local |= p[i];
    if (local) atomicOr(&flag, 1);
    __syncthreads();
    if (tid == 0) g_tok32 = (flag != 0) ? 1 : 0;
}

// ---------------------------------------------------------------------------
// SGEMM: C[dir] = A @ W[dir] + bias[dir]   (unchanged — isolation)
// ---------------------------------------------------------------------------
__global__ void __launch_bounds__(256) gemm_kernel(
    const float* __restrict__ embed,
    const void*  __restrict__ tokens,
    const float* __restrict__ W_fw,
    const float* __restrict__ W_bw,
    const float* __restrict__ b_fw,
    const float* __restrict__ b_bw,
    int mode)
{
    __shared__ __align__(16) float As[16][132];
    __shared__ __align__(16) float Bs[16][128];
    __shared__ int sTok[128];

    const int tid = threadIdx.x;
    const int dir = blockIdx.z;
    const int m0  = blockIdx.y * 128;
    const int n0  = blockIdx.x * 128;

    const float* Wm   = dir ? W_bw : W_fw;
    const float* bias = dir ? b_bw : b_fw;

    if (mode == 0 && tid < 128) {
        int r = m0 + tid;
        int s = r >> 6, b = r & 63;
        int tt = (dir == 0) ? s : (TSTEPS - 1 - s);
        sTok[tid] = load_token(tokens, g_tok32, b * TSTEPS + tt);
    }
    __syncthreads();

    const int ty = tid >> 4;
    const int tx = tid & 15;

    float acc[8][8];
#pragma unroll
    for (int i = 0; i < 8; i++)
#pragma unroll
        for (int j = 0; j < 8; j++) acc[i][j] = 0.f;

    for (int kt = 0; kt < KDIM; kt += 16) {
#pragma unroll
        for (int i = 0; i < 2; i++) {
            int idx = tid + i * 256;
            int m   = idx >> 2;
            int kq  = idx & 3;
            const float* arow;
            if (mode == 0) arow = embed + (size_t)sTok[m] * KDIM;
            else           arow = g_H1 + (size_t)dir * MROWS * HID + (size_t)(m0 + m) * HID;
            float4 v = *(const float4*)(arow + kt + kq * 4);
            As[kq * 4 + 0][m] = v.x;
            As[kq * 4 + 1][m] = v.y;
            As[kq * 4 + 2][m] = v.z;
            As[kq * 4 + 3][m] = v.w;
        }
#pragma unroll
        for (int i = 0; i < 2; i++) {
            int idx = tid + i * 256;
            int k   = idx >> 5;
            int nq  = idx & 31;
            *(float4*)&Bs[k][nq * 4] =
                *(const float4*)(Wm + (size_t)(kt + k) * NCOLS + n0 + nq * 4);
        }
        __syncthreads();

#pragma unroll
        for (int kk = 0; kk < 16; kk++) {
            float a[8], bb[8];
            *(float4*)&a[0]  = *(const float4*)&As[kk][ty * 8];
            *(float4*)&a[4]  = *(const float4*)&As[kk][ty * 8 + 4];
            *(float4*)&bb[0] = *(const float4*)&Bs[kk][tx * 8];
            *(float4*)&bb[4] = *(const float4*)&Bs[kk][tx * 8 + 4];
#pragma unroll
            for (int i = 0; i < 8; i++)
#pragma unroll
                for (int j = 0; j < 8; j++)
                    acc[i][j] = fmaf(a[i], bb[j], acc[i][j]);
        }
        __syncthreads();
    }

    float bv[8];
#pragma unroll
    for (int j = 0; j < 8; j++) bv[j] = bias[n0 + tx * 8 + j];

    float* Cd = g_Z + (size_t)dir * MROWS * NCOLS;
#pragma unroll
    for (int i = 0; i < 8; i++) {
        size_t r = (size_t)(m0 + ty * 8 + i);
        float* cp = Cd + r * NCOLS + n0 + tx * 8;
        float4 o0, o1;
        o0.x = acc[i][0] + bv[0]; o0.y = acc[i][1] + bv[1];
        o0.z = acc[i][2] + bv[2]; o0.w = acc[i][3] + bv[3];
        o1.x = acc[i][4] + bv[4]; o1.y = acc[i][5] + bv[5];
        o1.z = acc[i][6] + bv[6]; o1.w = acc[i][7] + bv[7];
        *(float4*)cp       = o0;
        *((float4*)cp + 1) = o1;
    }
}

// ---------------------------------------------------------------------------
// Recurrent phase. 128 CTAs x 256 thr. CTA = (dir, jb 0..31, bb 0..1).
// Compute identical to R4 (smem U + smem-staged h, broadcast LDS matvec).
// Sync: monotonic per-producer flags. flag[jb] = s+1 <=> CTA jb published
// h[s]. Publish: __syncthreads (intra-CTA HB) then ONE st.release.gpu by
// tid 0. Wait: warp 0 only — lane p acquires flags[p], ballot until all
// >= s; then __syncthreads releases the other 7 warps. No atomics, no
// threadfence, no winner hop. Double-buffered hT safe: flags >= s at step s
// => peers finished step s-1 => done reading slot s-2 (== s&1).
// ---------------------------------------------------------------------------
__global__ void __launch_bounds__(256, 1) rec_kernel(
    const float* __restrict__ U_fw,
    const float* __restrict__ U_bw,
    int layer)
{
    extern __shared__ float smem[];
    float* sU  = smem;                      // [k][jl] float4 of 4 gates: 8192 floats
    float* s_h = smem + NJ * 4 * KDIM;      // [k][bl]: 8192 floats

    const int cid = blockIdx.x;
    const int dir = cid >> 6;
    const int rem = cid & 63;
    const int jb  = rem >> 1;               // 0..31  (this CTA's flag index)
    const int bb  = rem & 1;                // 0..1
    const int j0  = jb * NJ;
    const int b0  = bb * NBL;
    const int tid = threadIdx.x;
    const int lane = tid & 31;
    const int bl  = tid >> 3;               // 0..31
    const int jl  = tid & 7;                // 0..7
    const int b   = b0 + bl;
    const int j   = j0 + jl;

    const int grp = dir * 2 + bb;
    unsigned* flags = g_flags[layer][grp];

    const float* U = dir ? U_bw : U_fw;

    // Cache U columns: sU[(k*NJ + jj)*4 + g] = U[k][g*HID + j0+jj]
    for (int idx = tid; idx < NJ * 4 * KDIM; idx += 256) {
        int g  = idx & 3;
        int jj = (idx >> 2) & (NJ - 1);
        int k  = idx >> 5;
        sU[idx] = U[(size_t)k * NCOLS + g * HID + j0 + jj];
    }
    __syncthreads();

    const float4* U4 = (const float4*)sU;
    const float* Zd  = g_Z + (size_t)dir * MROWS * NCOLS;
    float* Hd        = (layer ? g_H2 : g_H1) + (size_t)dir * MROWS * HID;
    float* hTdir0    = g_hT[0] + dir * 16384;
    float* hTdir1    = g_hT[1] + dir * 16384;

    // first-step Z
    size_t zrow0 = ((size_t)b) * NCOLS;
    float4 z;
    z.x = Zd[zrow0 + 0 * HID + j];
    z.y = Zd[zrow0 + 1 * HID + j];
    z.z = Zd[zrow0 + 2 * HID + j];
    z.w = Zd[zrow0 + 3 * HID + j];

    float c = 0.f;

    for (int s = 0; s < TSTEPS; s++) {
        float4 acc = z;

        if (s > 0) {
            // ---- wait: warp 0 polls the 32 producer flags; others park at bar
            if (tid < 32) {
                const unsigned tgt = (unsigned)s;
                while (__ballot_sync(FULLMASK, ld_acquire(&flags[lane]) < tgt)) { }
            }
            __syncthreads();                 // release warps 1-7; acquire HB to all

            // ---- fill s_h[k][bl] from g_hT[(s-1)&1] (straight float4 copy)
            const float* src = ((s - 1) & 1) ? hTdir1 : hTdir0;
#pragma unroll
            for (int i = 0; i < 8; i++) {
                int idx = tid + i * 256;            // 0..2047 float4s
                int jr  = idx >> 3;                 // k row 0..255
                int q   = idx & 7;
                float4 v = __ldcg((const float4*)(src + jr * 64 + b0) + q);
                *(float4*)&s_h[jr * NBL + q * 4] = v;
            }
            __syncthreads();

            // ---- matvec: z += h @ U (broadcast LDS, FFMA-bound)
#pragma unroll 16
            for (int k = 0; k < KDIM; k++) {
                float  hv = s_h[k * NBL + bl];
                float4 u  = U4[k * NJ + jl];
                acc.x = fmaf(u.x, hv, acc.x);
                acc.y = fmaf(u.y, hv, acc.y);
                acc.z = fmaf(u.z, hv, acc.z);
                acc.w = fmaf(u.w, hv, acc.w);
            }
        }

        // ---- activations ----
        float ig = fsig(acc.x);
        float fg = fsig(acc.y);
        float gg = ftanh_(acc.z);
        float og = fsig(acc.w);
        c = fg * c + ig * gg;
        float h = og * ftanh_(c);

        // publish h for next step (dbl-buffered, [j][b])
        float* hTbuf = (s & 1) ? hTdir1 : hTdir0;
        hTbuf[j * 64 + b] = h;

        __syncthreads();                      // all warps' hT stores done (HB)
        if (tid == 0 && s < TSTEPS - 1)
            st_release(&flags[jb], (unsigned)(s + 1));   // single-hop publish

        // off-critical-path work AFTER publish: sequence output + Z prefetch
        Hd[((size_t)s * NB + b) * HID + j] = h;
        if (s < TSTEPS - 1) {
            size_t zrow = ((size_t)(s + 1) * NB + b) * NCOLS;
            z.x = Zd[zrow + 0 * HID + j];
            z.y = Zd[zrow + 1 * HID + j];
            z.z = Zd[zrow + 2 * HID + j];
            z.w = Zd[zrow + 3 * HID + j];
        }
    }
}

// ---------------------------------------------------------------------------
// Output head: concat(fw, bw) @ dense_W + b, softmax over 5 classes.
// ---------------------------------------------------------------------------
__global__ void __launch_bounds__(256) dense_kernel(
    const float* __restrict__ Wd,
    const float* __restrict__ bd,
    float* __restrict__ out)
{
    __shared__ float sW[2 * HID * NCLASS];
    __shared__ float sb[NCLASS];
    const int tid = threadIdx.x;
    for (int i = tid; i < 2 * HID * NCLASS; i += 256) sW[i] = Wd[i];
    if (tid < NCLASS) sb[tid] = bd[tid];
    __syncthreads();

    int gid = blockIdx.x * 256 + tid;      // b*512 + t
    int b = gid >> 9, t = gid & 511;

    const float* hf = g_H2 + ((size_t)t * NB + b) * HID;
    const float* hb = g_H2 + (size_t)MROWS * HID + ((size_t)(TSTEPS - 1 - t) * NB + b) * HID;

    float acc[NCLASS];
#pragma unroll
    for (int cc = 0; cc < NCLASS; cc++) acc[cc] = sb[cc];

    for (int jj = 0; jj < HID; jj++) {
        float v = hf[jj];
#pragma unroll
        for (int cc = 0; cc < NCLASS; cc++)
            acc[cc] = fmaf(v, sW[jj * NCLASS + cc], acc[cc]);
    }
    for (int jj = 0; jj < HID; jj++) {
        float v = hb[jj];
#pragma unroll
        for (int cc = 0; cc < NCLASS; cc++)
            acc[cc] = fmaf(v, sW[(HID + jj) * NCLASS + cc], acc[cc]);
    }

    float m = acc[0];
#pragma unroll
    for (int cc = 1; cc < NCLASS; cc++) m = fmaxf(m, acc[cc]);
    float e[NCLASS], sum = 0.f;
#pragma unroll
    for (int cc = 0; cc < NCLASS; cc++) { e[cc] = __expf(acc[cc] - m); sum += e[cc]; }
    float inv = __fdividef(1.f, sum);
#pragma unroll
    for (int cc = 0; cc < NCLASS; cc++) out[(size_t)gid * NCLASS + cc] = e[cc] * inv;
}

// ---------------------------------------------------------------------------
// Launcher (graph-capturable: kernel launches only, default stream)
// ---------------------------------------------------------------------------
extern "C" void kernel_launch(void* const* d_in, const int* in_sizes, int n_in,
                              void* d_out, int out_size)
{
    const void*  tokens  = d_in[0];
    const float* embed   = (const float*)d_in[1];
    const float* fw_W1   = (const float*)d_in[2];
    const float* fw_U1   = (const float*)d_in[3];
    const float* fw_b1   = (const float*)d_in[4];
    const float* fw_W2   = (const float*)d_in[5];
    const float* fw_U2   = (const float*)d_in[6];
    const float* fw_b2   = (const float*)d_in[7];
    const float* bw_W1   = (const float*)d_in[8];
    const float* bw_U1   = (const float*)d_in[9];
    const float* bw_b1   = (const float*)d_in[10];
    const float* bw_W2   = (const float*)d_in[11];
    const float* bw_U2   = (const float*)d_in[12];
    const float* bw_b2   = (const float*)d_in[13];
    const float* dense_W = (const float*)d_in[14];
    const float* dense_b = (const float*)d_in[15];
    float* out = (float*)d_out;

    cudaFuncSetAttribute(rec_kernel, cudaFuncAttributeMaxDynamicSharedMemorySize, REC_SMEM);

    prep_kernel<<<1, 256>>>(tokens);

    gemm_kernel<<<dim3(8, 256, 2), 256>>>(embed, tokens, fw_W1, bw_W1, fw_b1, bw_b1, 0);
    rec_kernel<<<GRID_REC, 256, REC_SMEM>>>(fw_U1, bw_U1, 0);
    gemm_kernel<<<dim3(8, 256, 2), 256>>>(embed, tokens, fw_W2, bw_W2, fw_b2, bw_b2, 1);
    rec_kernel<<<GRID_REC, 256, REC_SMEM>>>(fw_U2, bw_U2, 1);
    dense_kernel<<<MROWS / 256, 256>>>(dense_W, dense_b, out);
}

// round 8
// speedup vs baseline: 2.1198x; 1.0089x over previous
#include <cuda_runtime.h>

// ---------------------------------------------------------------------------
// Problem dims
// ---------------------------------------------------------------------------
#define TSTEPS 512
#define NB     64
#define HID    256
#define MROWS  (TSTEPS * NB)      // 32768
#define NCOLS  1024               // 4*HID
#define KDIM   256
#define NCLASS 5

#define GRID_REC 128
#define NJ   8                     // j per CTA
#define NBL  32                    // batches per CTA
#define FULLMASK 0xffffffffu
#define REC_SMEM ((NJ * 4 * KDIM + KDIM * NBL) * 4)   // 32KB U + 32KB h

// ---------------------------------------------------------------------------
// Scratch (static __device__ arrays: allocation-free, allowed)
// ---------------------------------------------------------------------------
__device__ __align__(128) float g_Z [2u * MROWS * NCOLS];   // gate preactivations
__device__ __align__(128) float g_H1[2u * MROWS * HID];     // layer-1 hidden outputs
__device__ __align__(128) float g_H2[2u * MROWS * HID];     // layer-2 hidden outputs
__device__ __align__(128) float g_hT[2][2 * 16384];         // dbl-buffered h, [j][b], per dir
__device__ __align__(128) unsigned g_flags[2][4][32];       // [layer][group][producer jb]
__device__ int g_tok32 = 1;                                 // token dtype flag

// ---------------------------------------------------------------------------
// Single-hop message passing primitives
// ---------------------------------------------------------------------------
__device__ __forceinline__ unsigned ld_acquire(const unsigned* p) {
    unsigned v;
    asm volatile("ld.acquire.gpu.global.u32 %0, [%1];" : "=r"(v) : "l"(p) : "memory");
    return v;
}
__device__ __forceinline__ void st_release(unsigned* p, unsigned v) {
    asm volatile("st.release.gpu.global.u32 [%0], %1;" :: "l"(p), "r"(v) : "memory");
}

// ---------------------------------------------------------------------------
// Math helpers
// ---------------------------------------------------------------------------
__device__ __forceinline__ float fsig(float x) {
    x = fminf(fmaxf(x, -30.f), 30.f);
    return __fdividef(1.f, 1.f + __expf(-x));
}
__device__ __forceinline__ float ftanh_(float x) {
    x = fminf(fmaxf(x, -15.f), 15.f);
    float e = __expf(-2.f * x);
    return __fdividef(1.f - e, 1.f + e);
}
__device__ __forceinline__ int load_token(const void* tokens, int is32, int idx) {
    if (is32) return ((const int*)tokens)[idx];
    return (int)((const long long*)tokens)[idx];
}

// ---------------------------------------------------------------------------
// Prep: zero flags (graph replays reuse state) + token dtype probe.
// ---------------------------------------------------------------------------
__global__ void prep_kernel(const void* __restrict__ tokens) {
    __shared__ int flag;
    const int tid = threadIdx.x;
    if (tid < 256) ((unsigned*)g_flags)[tid] = 0u;
    if (tid == 0) flag = 0;
    __syncthreads();
    const int* p = (const int*)tokens;
    int local = 0;
    for (int i = 1 + 2 * tid; i < MROWS; i += 2 * 256) local |= p[i];
    if (local) atomicOr(&flag, 1);
    __syncthreads();
    if (tid == 0) g_tok32 = (flag != 0) ? 1 : 0;
}

// ---------------------------------------------------------------------------
// SGEMM: C[dir] = A @ W[dir] + bias[dir]   (unchanged — isolation)
// ---------------------------------------------------------------------------
__global__ void __launch_bounds__(256) gemm_kernel(
    const float* __restrict__ embed,
    const void*  __restrict__ tokens,
    const float* __restrict__ W_fw,
    const float* __restrict__ W_bw,
    const float* __restrict__ b_fw,
    const float* __restrict__ b_bw,
    int mode)
{
    __shared__ __align__(16) float As[16][132];
    __shared__ __align__(16) float Bs[16][128];
    __shared__ int sTok[128];

    const int tid = threadIdx.x;
    const int dir = blockIdx.z;
    const int m0  = blockIdx.y * 128;
    const int n0  = blockIdx.x * 128;

    const float* Wm   = dir ? W_bw : W_fw;
    const float* bias = dir ? b_bw : b_fw;

    if (mode == 0 && tid < 128) {
        int r = m0 + tid;
        int s = r >> 6, b = r & 63;
        int tt = (dir == 0) ? s : (TSTEPS - 1 - s);
        sTok[tid] = load_token(tokens, g_tok32, b * TSTEPS + tt);
    }
    __syncthreads();

    const int ty = tid >> 4;
    const int tx = tid & 15;

    float acc[8][8];
#pragma unroll
    for (int i = 0; i < 8; i++)
#pragma unroll
        for (int j = 0; j < 8; j++) acc[i][j] = 0.f;

    for (int kt = 0; kt < KDIM; kt += 16) {
#pragma unroll
        for (int i = 0; i < 2; i++) {
            int idx = tid + i * 256;
            int m   = idx >> 2;
            int kq  = idx & 3;
            const float* arow;
            if (mode == 0) arow = embed + (size_t)sTok[m] * KDIM;
            else           arow = g_H1 + (size_t)dir * MROWS * HID + (size_t)(m0 + m) * HID;
            float4 v = *(const float4*)(arow + kt + kq * 4);
            As[kq * 4 + 0][m] = v.x;
            As[kq * 4 + 1][m] = v.y;
            As[kq * 4 + 2][m] = v.z;
            As[kq * 4 + 3][m] = v.w;
        }
#pragma unroll
        for (int i = 0; i < 2; i++) {
            int idx = tid + i * 256;
            int k   = idx >> 5;
            int nq  = idx & 31;
            *(float4*)&Bs[k][nq * 4] =
                *(const float4*)(Wm + (size_t)(kt + k) * NCOLS + n0 + nq * 4);
        }
        __syncthreads();

#pragma unroll
        for (int kk = 0; kk < 16; kk++) {
            float a[8], bb[8];
            *(float4*)&a[0]  = *(const float4*)&As[kk][ty * 8];
            *(float4*)&a[4]  = *(const float4*)&As[kk][ty * 8 + 4];
            *(float4*)&bb[0] = *(const float4*)&Bs[kk][tx * 8];
            *(float4*)&bb[4] = *(const float4*)&Bs[kk][tx * 8 + 4];
#pragma unroll
            for (int i = 0; i < 8; i++)
#pragma unroll
                for (int j = 0; j < 8; j++)
                    acc[i][j] = fmaf(a[i], bb[j], acc[i][j]);
        }
        __syncthreads();
    }

    float bv[8];
#pragma unroll
    for (int j = 0; j < 8; j++) bv[j] = bias[n0 + tx * 8 + j];

    float* Cd = g_Z + (size_t)dir * MROWS * NCOLS;
#pragma unroll
    for (int i = 0; i < 8; i++) {
        size_t r = (size_t)(m0 + ty * 8 + i);
        float* cp = Cd + r * NCOLS + n0 + tx * 8;
        float4 o0, o1;
        o0.x = acc[i][0] + bv[0]; o0.y = acc[i][1] + bv[1];
        o0.z = acc[i][2] + bv[2]; o0.w = acc[i][3] + bv[3];
        o1.x = acc[i][4] + bv[4]; o1.y = acc[i][5] + bv[5];
        o1.z = acc[i][6] + bv[6]; o1.w = acc[i][7] + bv[7];
        *(float4*)cp       = o0;
        *((float4*)cp + 1) = o1;
    }
}

// ---------------------------------------------------------------------------
// Recurrent phase. 128 CTAs x 256 thr. CTA = (dir, jb 0..31, bb 0..1).
// Matvec now uses packed fma.rn.f32x2 (FFMA2): gate pairs (i,f) and (g,o)
// accumulated in b64 registers; per-k issue drops 6 -> 5 instructions and
// FFMA pipe work halves. Sync protocol identical to R6 (proven).
// ---------------------------------------------------------------------------
__global__ void __launch_bounds__(256, 1) rec_kernel(
    const float* __restrict__ U_fw,
    const float* __restrict__ U_bw,
    int layer)
{
    extern __shared__ float smem[];
    float* sU  = smem;                      // [k][jl] float4 of 4 gates: 8192 floats
    float* s_h = smem + NJ * 4 * KDIM;      // [k][bl]: 8192 floats

    const int cid = blockIdx.x;
    const int dir = cid >> 6;
    const int rem = cid & 63;
    const int jb  = rem >> 1;               // 0..31  (this CTA's flag index)
    const int bb  = rem & 1;                // 0..1
    const int j0  = jb * NJ;
    const int b0  = bb * NBL;
    const int tid = threadIdx.x;
    const int lane = tid & 31;
    const int bl  = tid >> 3;               // 0..31
    const int jl  = tid & 7;                // 0..7
    const int b   = b0 + bl;
    const int j   = j0 + jl;

    const int grp = dir * 2 + bb;
    unsigned* flags = g_flags[layer][grp];

    const float* U = dir ? U_bw : U_fw;

    // Cache U columns: sU[(k*NJ + jj)*4 + g] = U[k][g*HID + j0+jj]
    for (int idx = tid; idx < NJ * 4 * KDIM; idx += 256) {
        int g  = idx & 3;
        int jj = (idx >> 2) & (NJ - 1);
        int k  = idx >> 5;
        sU[idx] = U[(size_t)k * NCOLS + g * HID + j0 + jj];
    }
    __syncthreads();

    const unsigned sU_addr  = (unsigned)__cvta_generic_to_shared(sU);
    const unsigned sU_jlOff = sU_addr + (unsigned)(jl * 16);
    const float* Zd  = g_Z + (size_t)dir * MROWS * NCOLS;
    float* Hd        = (layer ? g_H2 : g_H1) + (size_t)dir * MROWS * HID;
    float* hTdir0    = g_hT[0] + dir * 16384;
    float* hTdir1    = g_hT[1] + dir * 16384;

    // first-step Z (streamed: no L2 reuse, keep hT resident)
    size_t zrow0 = ((size_t)b) * NCOLS;
    float4 z;
    z.x = __ldcs(&Zd[zrow0 + 0 * HID + j]);
    z.y = __ldcs(&Zd[zrow0 + 1 * HID + j]);
    z.z = __ldcs(&Zd[zrow0 + 2 * HID + j]);
    z.w = __ldcs(&Zd[zrow0 + 3 * HID + j]);

    float c = 0.f;

    for (int s = 0; s < TSTEPS; s++) {
        // pack z into FFMA2 accumulators: (i,f) and (g,o)
        unsigned long long acc01, acc23;
        asm("mov.b64 %0,{%1,%2};" : "=l"(acc01)
            : "r"(__float_as_uint(z.x)), "r"(__float_as_uint(z.y)));
        asm("mov.b64 %0,{%1,%2};" : "=l"(acc23)
            : "r"(__float_as_uint(z.z)), "r"(__float_as_uint(z.w)));

        if (s > 0) {
            // ---- wait: warp 0 polls the 32 producer flags; others park at bar
            if (tid < 32) {
                const unsigned tgt = (unsigned)s;
                while (__ballot_sync(FULLMASK, ld_acquire(&flags[lane]) < tgt)) { }
            }
            __syncthreads();                 // release warps 1-7; acquire HB

            // ---- fill s_h[k][bl] from g_hT[(s-1)&1] (straight float4 copy)
            const float* src = ((s - 1) & 1) ? hTdir1 : hTdir0;
#pragma unroll
            for (int i = 0; i < 8; i++) {
                int idx = tid + i * 256;            // 0..2047 float4s
                int jr  = idx >> 3;                 // k row 0..255
                int q   = idx & 7;
                float4 v = __ldcg((const float4*)(src + jr * 64 + b0) + q);
                *(float4*)&s_h[jr * NBL + q * 4] = v;
            }
            __syncthreads();

            // ---- matvec with packed FFMA2: per k = LDS + mov + LDS.v2.b64 + 2 FFMA2
#pragma unroll 16
            for (int k = 0; k < KDIM; k++) {
                float hv = s_h[k * NBL + bl];
                unsigned long long hh, u01, u23;
                asm("mov.b64 %0,{%1,%1};" : "=l"(hh) : "r"(__float_as_uint(hv)));
                asm("ld.shared.v2.b64 {%0,%1},[%2];" : "=l"(u01), "=l"(u23)
                    : "r"(sU_jlOff + (unsigned)(k * (NJ * 16))));
                asm("fma.rn.f32x2 %0, %1, %2, %0;" : "+l"(acc01) : "l"(u01), "l"(hh));
                asm("fma.rn.f32x2 %0, %1, %2, %0;" : "+l"(acc23) : "l"(u23), "l"(hh));
            }
        }

        // unpack accumulators
        unsigned r0, r1, r2, r3;
        asm("mov.b64 {%0,%1},%2;" : "=r"(r0), "=r"(r1) : "l"(acc01));
        asm("mov.b64 {%0,%1},%2;" : "=r"(r2), "=r"(r3) : "l"(acc23));

        // ---- activations ----
        float ig = fsig(__uint_as_float(r0));
        float fg = fsig(__uint_as_float(r1));
        float gg = ftanh_(__uint_as_float(r2));
        float og = fsig(__uint_as_float(r3));
        c = fg * c + ig * gg;
        float h = og * ftanh_(c);

        // publish h for next step (dbl-buffered, [j][b])
        float* hTbuf = (s & 1) ? hTdir1 : hTdir0;
        hTbuf[j * 64 + b] = h;

        __syncthreads();                      // all warps' hT stores done (HB)
        if (tid == 0 && s < TSTEPS - 1)
            st_release(&flags[jb], (unsigned)(s + 1));   // single-hop publish

        // off-critical-path: sequence output (streamed) + Z[s+1] prefetch
        __stcs(&Hd[((size_t)s * NB + b) * HID + j], h);
        if (s < TSTEPS - 1) {
            size_t zrow = ((size_t)(s + 1) * NB + b) * NCOLS;
            z.x = __ldcs(&Zd[zrow + 0 * HID + j]);
            z.y = __ldcs(&Zd[zrow + 1 * HID + j]);
            z.z = __ldcs(&Zd[zrow + 2 * HID + j]);
            z.w = __ldcs(&Zd[zrow + 3 * HID + j]);
        }
    }
}

// ---------------------------------------------------------------------------
// Output head: concat(fw, bw) @ dense_W + b, softmax over 5 classes.
// ---------------------------------------------------------------------------
__global__ void __launch_bounds__(256) dense_kernel(
    const float* __restrict__ Wd,
    const float* __restrict__ bd,
    float* __restrict__ out)
{
    __shared__ float sW[2 * HID * NCLASS];
    __shared__ float sb[NCLASS];
    const int tid = threadIdx.x;
    for (int i = tid; i < 2 * HID * NCLASS; i += 256) sW[i] = Wd[i];
    if (tid < NCLASS) sb[tid] = bd[tid];
    __syncthreads();

    int gid = blockIdx.x * 256 + tid;      // b*512 + t
    int b = gid >> 9, t = gid & 511;

    const float* hf = g_H2 + ((size_t)t * NB + b) * HID;
    const float* hb = g_H2 + (size_t)MROWS * HID + ((size_t)(TSTEPS - 1 - t) * NB + b) * HID;

    float acc[NCLASS];
#pragma unroll
    for (int cc = 0; cc < NCLASS; cc++) acc[cc] = sb[cc];

    for (int jj = 0; jj < HID; jj++) {
        float v = hf[jj];
#pragma unroll
        for (int cc = 0; cc < NCLASS; cc++)
            acc[cc] = fmaf(v, sW[jj * NCLASS + cc], acc[cc]);
    }
    for (int jj = 0; jj < HID; jj++) {
        float v = hb[jj];
#pragma unroll
        for (int cc = 0; cc < NCLASS; cc++)
            acc[cc] = fmaf(v, sW[(HID + jj) * NCLASS + cc], acc[cc]);
    }

    float m = acc[0];
#pragma unroll
    for (int cc = 1; cc < NCLASS; cc++) m = fmaxf(m, acc[cc]);
    float e[NCLASS], sum = 0.f;
#pragma unroll
    for (int cc = 0; cc < NCLASS; cc++) { e[cc] = __expf(acc[cc] - m); sum += e[cc]; }
    float inv = __fdividef(1.f, sum);
#pragma unroll
    for (int cc = 0; cc < NCLASS; cc++) out[(size_t)gid * NCLASS + cc] = e[cc] * inv;
}

// ---------------------------------------------------------------------------
// Launcher (graph-capturable: kernel launches only, default stream)
// ---------------------------------------------------------------------------
extern "C" void kernel_launch(void* const* d_in, const int* in_sizes, int n_in,
                              void* d_out, int out_size)
{
    const void*  tokens  = d_in[0];
    const float* embed   = (const float*)d_in[1];
    const float* fw_W1   = (const float*)d_in[2];
    const float* fw_U1   = (const float*)d_in[3];
    const float* fw_b1   = (const float*)d_in[4];
    const float* fw_W2   = (const float*)d_in[5];
    const float* fw_U2   = (const float*)d_in[6];
    const float* fw_b2   = (const float*)d_in[7];
    const float* bw_W1   = (const float*)d_in[8];
    const float* bw_U1   = (const float*)d_in[9];
    const float* bw_b1   = (const float*)d_in[10];
    const float* bw_W2   = (const float*)d_in[11];
    const float* bw_U2   = (const float*)d_in[12];
    const float* bw_b2   = (const float*)d_in[13];
    const float* dense_W = (const float*)d_in[14];
    const float* dense_b = (const float*)d_in[15];
    float* out = (float*)d_out;

    cudaFuncSetAttribute(rec_kernel, cudaFuncAttributeMaxDynamicSharedMemorySize, REC_SMEM);

    prep_kernel<<<1, 256>>>(tokens);

    gemm_kernel<<<dim3(8, 256, 2), 256>>>(embed, tokens, fw_W1, bw_W1, fw_b1, bw_b1, 0);
    rec_kernel<<<GRID_REC, 256, REC_SMEM>>>(fw_U1, bw_U1, 0);
    gemm_kernel<<<dim3(8, 256, 2), 256>>>(embed, tokens, fw_W2, bw_W2, fw_b2, bw_b2, 1);
    rec_kernel<<<GRID_REC, 256, REC_SMEM>>>(fw_U2, bw_U2, 1);
    dense_kernel<<<MROWS / 256, 256>>>(dense_W, dense_b, out);
}